// round 2
// baseline (speedup 1.0000x reference)
#include <cuda_runtime.h>
#include <math.h>

#define Bb 64
#define Tt 256
#define Hh 768

// ---------------- scratch (static device globals; no allocation) -------------
__device__ float g_whqT[(size_t)Bb*Tt*Tt];   // whqT[b][i][j] = sum_h q[b,j,h]*Wc1[h,i]
__device__ float g_whp [(size_t)Bb*Tt*Tt];   // whp [b][i][j] = sum_h p[b,i,h]*Wc2[h,j]
__device__ float g_pb  [(size_t)Bb*Tt*Hh];   // p @ Wb
__device__ float g_Sb  [(size_t)Bb*Tt*Tt];   // bilinear scores (raw)
__device__ float g_Sd  [(size_t)Bb*Tt*Tt];   // elemwise-product scores (tanh*vd applied)
__device__ float g_P   [(size_t)4*Bb*Tt*Tt]; // softmax probabilities, 4 types
__device__ float g_qWm[Bb*Tt];
__device__ float g_pWm[Bb*Tt];

// ---------------- K0: qWm[b,t] = q[b,t,:]@Wm ; pWm likewise ------------------
__global__ void k_vec(const float* __restrict__ q, const float* __restrict__ p,
                      const float* __restrict__ Wm) {
    int b = blockIdx.y, t = blockIdx.x, tid = threadIdx.x;
    const float* qr = q + ((size_t)b*Tt + t)*Hh;
    const float* pr = p + ((size_t)b*Tt + t)*Hh;
    float sq = 0.f, sp = 0.f;
    for (int h = tid; h < Hh; h += 256) {
        float w = Wm[h];
        sq += qr[h]*w; sp += pr[h]*w;
    }
    for (int o = 16; o; o >>= 1) {
        sq += __shfl_down_sync(0xffffffffu, sq, o);
        sp += __shfl_down_sync(0xffffffffu, sp, o);
    }
    __shared__ float ssq[8], ssp[8];
    int w = tid >> 5, l = tid & 31;
    if (!l) { ssq[w] = sq; ssp[w] = sp; }
    __syncthreads();
    if (tid == 0) {
        float a = 0.f, c = 0.f;
        for (int i = 0; i < 8; i++) { a += ssq[i]; c += ssp[i]; }
        g_qWm[b*Tt + t] = a;
        g_pWm[b*Tt + t] = c;
    }
}

// ---------------- K1: C[b] = A[b](TxH) @ W(HxN), K=768 -----------------------
// mode 0: C=g_whqT, N=T, store TRANSPOSED; mode 1: C=g_whp, N=T; mode 2: C=g_pb, N=H
__global__ void gemm_aw(const float* __restrict__ A, const float* __restrict__ W,
                        int N, int mode) {
    float* C = (mode == 0) ? g_whqT : (mode == 1) ? g_whp : g_pb;
    int b = blockIdx.z;
    int m0 = blockIdx.y * 64, n0 = blockIdx.x * 64;
    const float* Ab = A + (size_t)b*Tt*Hh;
    __shared__ float As[16][64], Bs[16][64];
    int tid = threadIdx.x;
    int tx = tid & 15, ty = tid >> 4;
    int lrow = tid >> 2, lc4 = (tid & 3) * 4;
    int brow = tid >> 6, bcol = tid & 63;
    float acc[4][4] = {};
    for (int k0 = 0; k0 < Hh; k0 += 16) {
        float4 a = *(const float4*)&Ab[(size_t)(m0 + lrow)*Hh + k0 + lc4];
        As[lc4+0][lrow] = a.x; As[lc4+1][lrow] = a.y;
        As[lc4+2][lrow] = a.z; As[lc4+3][lrow] = a.w;
        #pragma unroll
        for (int i = 0; i < 4; i++)
            Bs[brow + i*4][bcol] = W[(size_t)(k0 + brow + i*4)*N + n0 + bcol];
        __syncthreads();
        #pragma unroll
        for (int k = 0; k < 16; k++) {
            float4 av = *(const float4*)&As[k][ty*4];
            float4 bv = *(const float4*)&Bs[k][tx*4];
            float ar[4] = {av.x, av.y, av.z, av.w};
            float br[4] = {bv.x, bv.y, bv.z, bv.w};
            #pragma unroll
            for (int i = 0; i < 4; i++)
                #pragma unroll
                for (int j = 0; j < 4; j++)
                    acc[i][j] += ar[i]*br[j];
        }
        __syncthreads();
    }
    if (mode == 0) {  // transposed store: C[b][n][m]
        size_t base = (size_t)b*Tt*Tt;
        #pragma unroll
        for (int i = 0; i < 4; i++)
            #pragma unroll
            for (int j = 0; j < 4; j++)
                C[base + (size_t)(n0 + tx*4 + j)*Tt + (m0 + ty*4 + i)] = acc[i][j];
    } else {
        size_t base = (size_t)b*Tt*(size_t)N;
        #pragma unroll
        for (int i = 0; i < 4; i++)
            #pragma unroll
            for (int j = 0; j < 4; j++)
                C[base + (size_t)(m0 + ty*4 + i)*N + (n0 + tx*4 + j)] = acc[i][j];
    }
}

// ---------------- K2: dual NT GEMM: Sb = pb@q^T, Sd_raw = (p*Wd)@q^T ---------
__global__ void gemm_bt2(const float* __restrict__ p, const float* __restrict__ q,
                         const float* __restrict__ Wd, const float* __restrict__ vd) {
    int b = blockIdx.z;
    int m0 = blockIdx.y * 64, n0 = blockIdx.x * 64;
    const float* pbb = g_pb + (size_t)b*Tt*Hh;
    const float* pr  = p   + (size_t)b*Tt*Hh;
    const float* qr  = q   + (size_t)b*Tt*Hh;
    __shared__ float As1[16][64], As2[16][64], Bs[16][64];
    int tid = threadIdx.x;
    int tx = tid & 15, ty = tid >> 4;
    int lrow = tid >> 2, lc4 = (tid & 3) * 4;
    float ab[4][4] = {}, ad[4][4] = {};
    for (int k0 = 0; k0 < Hh; k0 += 16) {
        float4 a1 = *(const float4*)&pbb[(size_t)(m0 + lrow)*Hh + k0 + lc4];
        float4 a2 = *(const float4*)&pr [(size_t)(m0 + lrow)*Hh + k0 + lc4];
        float4 wd = *(const float4*)&Wd[k0 + lc4];
        a2.x *= wd.x; a2.y *= wd.y; a2.z *= wd.z; a2.w *= wd.w;
        float4 bq = *(const float4*)&qr[(size_t)(n0 + lrow)*Hh + k0 + lc4];
        As1[lc4+0][lrow] = a1.x; As1[lc4+1][lrow] = a1.y;
        As1[lc4+2][lrow] = a1.z; As1[lc4+3][lrow] = a1.w;
        As2[lc4+0][lrow] = a2.x; As2[lc4+1][lrow] = a2.y;
        As2[lc4+2][lrow] = a2.z; As2[lc4+3][lrow] = a2.w;
        Bs [lc4+0][lrow] = bq.x; Bs [lc4+1][lrow] = bq.y;
        Bs [lc4+2][lrow] = bq.z; Bs [lc4+3][lrow] = bq.w;
        __syncthreads();
        #pragma unroll
        for (int k = 0; k < 16; k++) {
            float4 a1v = *(const float4*)&As1[k][ty*4];
            float4 a2v = *(const float4*)&As2[k][ty*4];
            float4 bv  = *(const float4*)&Bs [k][tx*4];
            float a1r[4] = {a1v.x, a1v.y, a1v.z, a1v.w};
            float a2r[4] = {a2v.x, a2v.y, a2v.z, a2v.w};
            float br[4]  = {bv.x,  bv.y,  bv.z,  bv.w};
            #pragma unroll
            for (int i = 0; i < 4; i++)
                #pragma unroll
                for (int j = 0; j < 4; j++) {
                    ab[i][j] += a1r[i]*br[j];
                    ad[i][j] += a2r[i]*br[j];
                }
        }
        __syncthreads();
    }
    size_t base = (size_t)b*Tt*Tt;
    #pragma unroll
    for (int i = 0; i < 4; i++)
        #pragma unroll
        for (int j = 0; j < 4; j++) {
            int m = m0 + ty*4 + i, n = n0 + tx*4 + j;
            g_Sb[base + (size_t)m*Tt + n] = ab[i][j];
            g_Sd[base + (size_t)m*Tt + n] = tanhf(ad[i][j]) * vd[n];  // vd scales col j
        }
}

// ---------------- K3: finish scores + row softmax -> g_P ---------------------
// mode 0 (qc): tanh(whp + whqT) * vc[i]   (vc scales row i)
// mode 1 (qb): g_Sb raw
// mode 2 (qd): g_Sd (finished)
// mode 3 (qm): tanh(qWm[j] - pWm[i]) * vm[j]
__global__ void k_softmax(const float* __restrict__ vc, const float* __restrict__ vm) {
    int mode = blockIdx.z, b = blockIdx.y, i = blockIdx.x, j = threadIdx.x;
    size_t base = (size_t)b*Tt*Tt + (size_t)i*Tt;
    float s;
    if      (mode == 0) s = tanhf(g_whp[base + j] + g_whqT[base + j]) * vc[i];
    else if (mode == 1) s = g_Sb[base + j];
    else if (mode == 2) s = g_Sd[base + j];
    else                s = tanhf(g_qWm[b*Tt + j] - g_pWm[b*Tt + i]) * vm[j];

    float m = s;
    for (int o = 16; o; o >>= 1) m = fmaxf(m, __shfl_xor_sync(0xffffffffu, m, o));
    __shared__ float rm[8], rs[8];
    int w = j >> 5, l = j & 31;
    if (!l) rm[w] = m;
    __syncthreads();
    float mm = rm[0];
    #pragma unroll
    for (int k = 1; k < 8; k++) mm = fmaxf(mm, rm[k]);

    float e = __expf(s - mm);
    float sum = e;
    for (int o = 16; o; o >>= 1) sum += __shfl_xor_sync(0xffffffffu, sum, o);
    if (!l) rs[w] = sum;
    __syncthreads();
    float tot = 0.f;
    #pragma unroll
    for (int k = 0; k < 8; k++) tot += rs[k];

    g_P[(size_t)mode*Bb*Tt*Tt + base + j] = e / tot;
}

// ---------------- K4: out[type][b] = P[type][b](TxT) @ q[b](TxH) -------------
__global__ void gemm_out(const float* __restrict__ q, float* __restrict__ out) {
    int z = blockIdx.z;            // 0..255
    int type = z >> 6, b = z & 63;
    int m0 = blockIdx.y * 64, n0 = blockIdx.x * 64;
    const float* A  = g_P + (size_t)type*Bb*Tt*Tt + (size_t)b*Tt*Tt;
    const float* Bm = q + (size_t)b*Tt*Hh;
    float* C = out + (size_t)type*Bb*Tt*Hh + (size_t)b*Tt*Hh;
    __shared__ float As[16][64], Bs[16][64];
    int tid = threadIdx.x;
    int tx = tid & 15, ty = tid >> 4;
    int lrow = tid >> 2, lc4 = (tid & 3) * 4;
    int brow = tid >> 6, bcol = tid & 63;
    float acc[4][4] = {};
    for (int k0 = 0; k0 < Tt; k0 += 16) {
        float4 a = *(const float4*)&A[(size_t)(m0 + lrow)*Tt + k0 + lc4];
        As[lc4+0][lrow] = a.x; As[lc4+1][lrow] = a.y;
        As[lc4+2][lrow] = a.z; As[lc4+3][lrow] = a.w;
        #pragma unroll
        for (int i = 0; i < 4; i++)
            Bs[brow + i*4][bcol] = Bm[(size_t)(k0 + brow + i*4)*Hh + n0 + bcol];
        __syncthreads();
        #pragma unroll
        for (int k = 0; k < 16; k++) {
            float4 av = *(const float4*)&As[k][ty*4];
            float4 bv = *(const float4*)&Bs[k][tx*4];
            float ar[4] = {av.x, av.y, av.z, av.w};
            float br[4] = {bv.x, bv.y, bv.z, bv.w};
            #pragma unroll
            for (int i = 0; i < 4; i++)
                #pragma unroll
                for (int j = 0; j < 4; j++)
                    acc[i][j] += ar[i]*br[j];
        }
        __syncthreads();
    }
    #pragma unroll
    for (int i = 0; i < 4; i++)
        #pragma unroll
        for (int j = 0; j < 4; j++)
            C[(size_t)(m0 + ty*4 + i)*Hh + (n0 + tx*4 + j)] = acc[i][j];
}

// ---------------- launch -----------------------------------------------------
extern "C" void kernel_launch(void* const* d_in, const int* in_sizes, int n_in,
                              void* d_out, int out_size) {
    const float* q   = (const float*)d_in[0];
    const float* p   = (const float*)d_in[1];
    const float* Wc1 = (const float*)d_in[2];
    const float* Wc2 = (const float*)d_in[3];
    const float* vc  = (const float*)d_in[4];
    const float* Wb  = (const float*)d_in[5];
    const float* Wd  = (const float*)d_in[6];
    const float* vd  = (const float*)d_in[7];
    const float* Wm  = (const float*)d_in[8];
    const float* vm  = (const float*)d_in[9];
    float* out = (float*)d_out;

    k_vec   <<<dim3(Tt, Bb), 256>>>(q, p, Wm);
    gemm_aw <<<dim3(4, 4, Bb), 256>>>(q, Wc1, Tt, 0);   // whqT (transposed store)
    gemm_aw <<<dim3(4, 4, Bb), 256>>>(p, Wc2, Tt, 1);   // whp
    gemm_aw <<<dim3(12, 4, Bb), 256>>>(p, Wb, Hh, 2);   // pb = p@Wb
    gemm_bt2<<<dim3(4, 4, Bb), 256>>>(p, q, Wd, vd);    // Sb, Sd
    k_softmax<<<dim3(Tt, Bb, 4), 256>>>(vc, vm);        // 4x softmax -> g_P
    gemm_out<<<dim3(12, 4, 4*Bb), 256>>>(q, out);       // 4x P@q -> out
}

// round 6
// speedup vs baseline: 1.0066x; 1.0066x over previous
#include <cuda_runtime.h>
#include <cstdint>
#include <math.h>

#define Bb 64
#define Tt 256
#define Hh 768

// ---------------- packed f32x2 helpers (sm_100+ base PTX, not 'a'-gated) -----
__device__ __forceinline__ void ffma2(uint64_t& d, uint64_t a, uint64_t b) {
    asm("fma.rn.f32x2 %0, %1, %2, %0;" : "+l"(d) : "l"(a), "l"(b));
}
__device__ __forceinline__ uint64_t bcast2(float x) {
    uint64_t r;
    asm("mov.b64 %0, {%1, %1};" : "=l"(r) : "f"(x));
    return r;
}
__device__ __forceinline__ void unpack2(uint64_t v, float& lo, float& hi) {
    asm("mov.b64 {%0, %1}, %2;" : "=f"(lo), "=f"(hi) : "l"(v));
}
union F4U2 { float4 f; uint64_t u[2]; };

// ---------------- scratch (static device globals; no allocation) -------------
__device__ float g_whqT[(size_t)Bb*Tt*Tt];   // whqT[b][i][j] = sum_h q[b,j,h]*Wc1[h,i]
__device__ float g_whp [(size_t)Bb*Tt*Tt];   // whp [b][i][j] = sum_h p[b,i,h]*Wc2[h,j]
__device__ float g_pb  [(size_t)Bb*Tt*Hh];   // p @ Wb
__device__ float g_Sb  [(size_t)Bb*Tt*Tt];   // bilinear scores (raw)
__device__ float g_Sd  [(size_t)Bb*Tt*Tt];   // elemwise-product scores (finished)
__device__ float g_P   [(size_t)4*Bb*Tt*Tt]; // softmax probabilities, 4 types
__device__ float g_qWm[Bb*Tt];
__device__ float g_pWm[Bb*Tt];

// ---------------- K0: qWm[b,t] = q[b,t,:]@Wm ; pWm likewise ------------------
__global__ void k_vec(const float* __restrict__ q, const float* __restrict__ p,
                      const float* __restrict__ Wm) {
    int b = blockIdx.y, t = blockIdx.x, tid = threadIdx.x;
    const float* qr = q + ((size_t)b*Tt + t)*Hh;
    const float* pr = p + ((size_t)b*Tt + t)*Hh;
    float sq = 0.f, sp = 0.f;
    for (int h = tid; h < Hh; h += 256) {
        float w = Wm[h];
        sq += qr[h]*w; sp += pr[h]*w;
    }
    for (int o = 16; o; o >>= 1) {
        sq += __shfl_down_sync(0xffffffffu, sq, o);
        sp += __shfl_down_sync(0xffffffffu, sp, o);
    }
    __shared__ float ssq[8], ssp[8];
    int w = tid >> 5, l = tid & 31;
    if (!l) { ssq[w] = sq; ssp[w] = sp; }
    __syncthreads();
    if (tid == 0) {
        float a = 0.f, c = 0.f;
        for (int i = 0; i < 8; i++) { a += ssq[i]; c += ssp[i]; }
        g_qWm[b*Tt + t] = a;
        g_pWm[b*Tt + t] = c;
    }
}

// ---------------- K1: C[b] = A[b](TxH) @ W(HxN), K=768, f32x2 FMA ------------
// mode 0: C=g_whqT, N=T, store TRANSPOSED; mode 1: C=g_whp, N=T; mode 2: C=g_pb, N=H
__global__ void gemm_aw(const float* __restrict__ A, const float* __restrict__ W,
                        int N, int mode) {
    float* C = (mode == 0) ? g_whqT : (mode == 1) ? g_whp : g_pb;
    int b = blockIdx.z;
    int m0 = blockIdx.y * 64, n0 = blockIdx.x * 64;
    const float* Ab = A + (size_t)b*Tt*Hh;
    __shared__ float As[16][64], Bs[16][64];
    int tid = threadIdx.x;
    int tx = tid & 15, ty = tid >> 4;
    int lrow = tid >> 2, lc4 = (tid & 3) * 4;
    int brow = tid >> 6, bcol = tid & 63;
    uint64_t acc[4][2] = {};          // acc[i][jp] = (c[i][2jp], c[i][2jp+1])
    for (int k0 = 0; k0 < Hh; k0 += 16) {
        float4 a = *(const float4*)&Ab[(size_t)(m0 + lrow)*Hh + k0 + lc4];
        As[lc4+0][lrow] = a.x; As[lc4+1][lrow] = a.y;
        As[lc4+2][lrow] = a.z; As[lc4+3][lrow] = a.w;
        #pragma unroll
        for (int i = 0; i < 4; i++)
            Bs[brow + i*4][bcol] = W[(size_t)(k0 + brow + i*4)*N + n0 + bcol];
        __syncthreads();
        #pragma unroll
        for (int k = 0; k < 16; k++) {
            float4 av = *(const float4*)&As[k][ty*4];
            F4U2 bv; bv.f = *(const float4*)&Bs[k][tx*4];
            float ar[4] = {av.x, av.y, av.z, av.w};
            #pragma unroll
            for (int i = 0; i < 4; i++) {
                uint64_t aa = bcast2(ar[i]);
                ffma2(acc[i][0], aa, bv.u[0]);
                ffma2(acc[i][1], aa, bv.u[1]);
            }
        }
        __syncthreads();
    }
    if (mode == 0) {  // transposed store: C[b][n][m]
        size_t base = (size_t)b*Tt*Tt;
        #pragma unroll
        for (int i = 0; i < 4; i++)
            #pragma unroll
            for (int jp = 0; jp < 2; jp++) {
                float c0, c1; unpack2(acc[i][jp], c0, c1);
                C[base + (size_t)(n0 + tx*4 + jp*2 + 0)*Tt + (m0 + ty*4 + i)] = c0;
                C[base + (size_t)(n0 + tx*4 + jp*2 + 1)*Tt + (m0 + ty*4 + i)] = c1;
            }
    } else {
        size_t base = (size_t)b*Tt*(size_t)N;
        #pragma unroll
        for (int i = 0; i < 4; i++)
            #pragma unroll
            for (int jp = 0; jp < 2; jp++) {
                float c0, c1; unpack2(acc[i][jp], c0, c1);
                size_t r = base + (size_t)(m0 + ty*4 + i)*N + (n0 + tx*4 + jp*2);
                C[r + 0] = c0;
                C[r + 1] = c1;
            }
    }
}

// ---------------- K2: dual NT GEMM: Sb = pb@q^T, Sd_raw = (p*Wd)@q^T ---------
__global__ void gemm_bt2(const float* __restrict__ p, const float* __restrict__ q,
                         const float* __restrict__ Wd, const float* __restrict__ vd) {
    int b = blockIdx.z;
    int m0 = blockIdx.y * 64, n0 = blockIdx.x * 64;
    const float* pbb = g_pb + (size_t)b*Tt*Hh;
    const float* pr  = p   + (size_t)b*Tt*Hh;
    const float* qr  = q   + (size_t)b*Tt*Hh;
    __shared__ float As1[16][64], As2[16][64], Bs[16][64];
    int tid = threadIdx.x;
    int tx = tid & 15, ty = tid >> 4;
    int lrow = tid >> 2, lc4 = (tid & 3) * 4;
    uint64_t ab[4][2] = {}, ad[4][2] = {};
    for (int k0 = 0; k0 < Hh; k0 += 16) {
        float4 a1 = *(const float4*)&pbb[(size_t)(m0 + lrow)*Hh + k0 + lc4];
        float4 a2 = *(const float4*)&pr [(size_t)(m0 + lrow)*Hh + k0 + lc4];
        float4 wd = *(const float4*)&Wd[k0 + lc4];
        a2.x *= wd.x; a2.y *= wd.y; a2.z *= wd.z; a2.w *= wd.w;
        float4 bq = *(const float4*)&qr[(size_t)(n0 + lrow)*Hh + k0 + lc4];
        As1[lc4+0][lrow] = a1.x; As1[lc4+1][lrow] = a1.y;
        As1[lc4+2][lrow] = a1.z; As1[lc4+3][lrow] = a1.w;
        As2[lc4+0][lrow] = a2.x; As2[lc4+1][lrow] = a2.y;
        As2[lc4+2][lrow] = a2.z; As2[lc4+3][lrow] = a2.w;
        Bs [lc4+0][lrow] = bq.x; Bs [lc4+1][lrow] = bq.y;
        Bs [lc4+2][lrow] = bq.z; Bs [lc4+3][lrow] = bq.w;
        __syncthreads();
        #pragma unroll
        for (int k = 0; k < 16; k++) {
            float4 a1v = *(const float4*)&As1[k][ty*4];
            float4 a2v = *(const float4*)&As2[k][ty*4];
            F4U2 bv; bv.f = *(const float4*)&Bs[k][tx*4];
            float a1r[4] = {a1v.x, a1v.y, a1v.z, a1v.w};
            float a2r[4] = {a2v.x, a2v.y, a2v.z, a2v.w};
            #pragma unroll
            for (int i = 0; i < 4; i++) {
                uint64_t aa1 = bcast2(a1r[i]);
                uint64_t aa2 = bcast2(a2r[i]);
                ffma2(ab[i][0], aa1, bv.u[0]);
                ffma2(ab[i][1], aa1, bv.u[1]);
                ffma2(ad[i][0], aa2, bv.u[0]);
                ffma2(ad[i][1], aa2, bv.u[1]);
            }
        }
        __syncthreads();
    }
    size_t base = (size_t)b*Tt*Tt;
    #pragma unroll
    for (int i = 0; i < 4; i++)
        #pragma unroll
        for (int jp = 0; jp < 2; jp++) {
            int m = m0 + ty*4 + i, n = n0 + tx*4 + jp*2;
            float b0, b1; unpack2(ab[i][jp], b0, b1);
            float d0, d1; unpack2(ad[i][jp], d0, d1);
            g_Sb[base + (size_t)m*Tt + n + 0] = b0;
            g_Sb[base + (size_t)m*Tt + n + 1] = b1;
            g_Sd[base + (size_t)m*Tt + n + 0] = tanhf(d0) * vd[n + 0];
            g_Sd[base + (size_t)m*Tt + n + 1] = tanhf(d1) * vd[n + 1];
        }
}

// ---------------- K3: finish scores + row softmax -> g_P ---------------------
__global__ void k_softmax(const float* __restrict__ vc, const float* __restrict__ vm) {
    int mode = blockIdx.z, b = blockIdx.y, i = blockIdx.x, j = threadIdx.x;
    size_t base = (size_t)b*Tt*Tt + (size_t)i*Tt;
    float s;
    if      (mode == 0) s = tanhf(g_whp[base + j] + g_whqT[base + j]) * vc[i];
    else if (mode == 1) s = g_Sb[base + j];
    else if (mode == 2) s = g_Sd[base + j];
    else                s = tanhf(g_qWm[b*Tt + j] - g_pWm[b*Tt + i]) * vm[j];

    float m = s;
    for (int o = 16; o; o >>= 1) m = fmaxf(m, __shfl_xor_sync(0xffffffffu, m, o));
    __shared__ float rm[8], rs[8];
    int w = j >> 5, l = j & 31;
    if (!l) rm[w] = m;
    __syncthreads();
    float mm = rm[0];
    #pragma unroll
    for (int k = 1; k < 8; k++) mm = fmaxf(mm, rm[k]);

    float e = __expf(s - mm);
    float sum = e;
    for (int o = 16; o; o >>= 1) sum += __shfl_xor_sync(0xffffffffu, sum, o);
    if (!l) rs[w] = sum;
    __syncthreads();
    float tot = 0.f;
    #pragma unroll
    for (int k = 0; k < 8; k++) tot += rs[k];

    g_P[(size_t)mode*Bb*Tt*Tt + base + j] = e / tot;
}

// ---------------- K4: out[type][b] = P[type][b](TxT) @ q[b](TxH) -------------
__global__ void gemm_out(const float* __restrict__ q, float* __restrict__ out) {
    int z = blockIdx.z;            // 0..255
    int type = z >> 6, b = z & 63;
    int m0 = blockIdx.y * 64, n0 = blockIdx.x * 64;
    const float* A  = g_P + (size_t)type*Bb*Tt*Tt + (size_t)b*Tt*Tt;
    const float* Bm = q + (size_t)b*Tt*Hh;
    float* C = out + (size_t)type*Bb*Tt*Hh + (size_t)b*Tt*Hh;
    __shared__ float As[16][64], Bs[16][64];
    int tid = threadIdx.x;
    int tx = tid & 15, ty = tid >> 4;
    int lrow = tid >> 2, lc4 = (tid & 3) * 4;
    int brow = tid >> 6, bcol = tid & 63;
    uint64_t acc[4][2] = {};
    for (int k0 = 0; k0 < Tt; k0 += 16) {
        float4 a = *(const float4*)&A[(size_t)(m0 + lrow)*Tt + k0 + lc4];
        As[lc4+0][lrow] = a.x; As[lc4+1][lrow] = a.y;
        As[lc4+2][lrow] = a.z; As[lc4+3][lrow] = a.w;
        #pragma unroll
        for (int i = 0; i < 4; i++)
            Bs[brow + i*4][bcol] = Bm[(size_t)(k0 + brow + i*4)*Hh + n0 + bcol];
        __syncthreads();
        #pragma unroll
        for (int k = 0; k < 16; k++) {
            float4 av = *(const float4*)&As[k][ty*4];
            F4U2 bv; bv.f = *(const float4*)&Bs[k][tx*4];
            float ar[4] = {av.x, av.y, av.z, av.w};
            #pragma unroll
            for (int i = 0; i < 4; i++) {
                uint64_t aa = bcast2(ar[i]);
                ffma2(acc[i][0], aa, bv.u[0]);
                ffma2(acc[i][1], aa, bv.u[1]);
            }
        }
        __syncthreads();
    }
    #pragma unroll
    for (int i = 0; i < 4; i++)
        #pragma unroll
        for (int jp = 0; jp < 2; jp++) {
            float c0, c1; unpack2(acc[i][jp], c0, c1);
            size_t r = (size_t)(m0 + ty*4 + i)*Hh + (n0 + tx*4 + jp*2);
            C[r + 0] = c0;
            C[r + 1] = c1;
        }
}

// ---------------- launch -----------------------------------------------------
extern "C" void kernel_launch(void* const* d_in, const int* in_sizes, int n_in,
                              void* d_out, int out_size) {
    const float* q   = (const float*)d_in[0];
    const float* p   = (const float*)d_in[1];
    const float* Wc1 = (const float*)d_in[2];
    const float* Wc2 = (const float*)d_in[3];
    const float* vc  = (const float*)d_in[4];
    const float* Wb  = (const float*)d_in[5];
    const float* Wd  = (const float*)d_in[6];
    const float* vd  = (const float*)d_in[7];
    const float* Wm  = (const float*)d_in[8];
    const float* vm  = (const float*)d_in[9];
    float* out = (float*)d_out;

    k_vec   <<<dim3(Tt, Bb), 256>>>(q, p, Wm);
    gemm_aw <<<dim3(4, 4, Bb), 256>>>(q, Wc1, Tt, 0);   // whqT (transposed store)
    gemm_aw <<<dim3(4, 4, Bb), 256>>>(p, Wc2, Tt, 1);   // whp
    gemm_aw <<<dim3(12, 4, Bb), 256>>>(p, Wb, Hh, 2);   // pb = p@Wb
    gemm_bt2<<<dim3(4, 4, Bb), 256>>>(p, q, Wd, vd);    // Sb, Sd
    k_softmax<<<dim3(Tt, Bb, 4), 256>>>(vc, vm);        // 4x softmax -> g_P
    gemm_out<<<dim3(12, 4, 4*Bb), 256>>>(q, out);       // 4x P@q -> out
}

// round 9
// speedup vs baseline: 1.2942x; 1.2858x over previous
#include <cuda_runtime.h>
#include <cstdint>
#include <math.h>

#define Bb 64
#define Tt 256
#define Hh 768
#define KB 16

// ---------------- packed f32x2 helpers (sm_100+ base PTX, not 'a'-gated) -----
__device__ __forceinline__ void ffma2(uint64_t& d, uint64_t a, uint64_t b) {
    asm("fma.rn.f32x2 %0, %1, %2, %0;" : "+l"(d) : "l"(a), "l"(b));
}
__device__ __forceinline__ uint64_t bcast2(float x) {
    uint64_t r;
    asm("mov.b64 %0, {%1, %1};" : "=l"(r) : "f"(x));
    return r;
}
__device__ __forceinline__ void unpack2(uint64_t v, float& lo, float& hi) {
    asm("mov.b64 {%0, %1}, %2;" : "=f"(lo), "=f"(hi) : "l"(v));
}
union F4U2 { float4 f; uint64_t u[2]; };

// ---------------- scratch (static device globals; no allocation) -------------
__device__ float g_whqT[(size_t)Bb*Tt*Tt];   // whqT[b][i][j] = whq[b][j][i]
__device__ float g_whp [(size_t)Bb*Tt*Tt];
__device__ float g_pb  [(size_t)Bb*Tt*Hh];
__device__ float g_Sb  [(size_t)Bb*Tt*Tt];
__device__ float g_Sd  [(size_t)Bb*Tt*Tt];
__device__ float g_P   [(size_t)4*Bb*Tt*Tt];
__device__ float g_qWm[Bb*Tt];
__device__ float g_pWm[Bb*Tt];

// ---------------- K0: qWm[b,t] = q[b,t,:]@Wm ; pWm likewise ------------------
__global__ void k_vec(const float* __restrict__ q, const float* __restrict__ p,
                      const float* __restrict__ Wm) {
    int b = blockIdx.y, t = blockIdx.x, tid = threadIdx.x;
    const float* qr = q + ((size_t)b*Tt + t)*Hh;
    const float* pr = p + ((size_t)b*Tt + t)*Hh;
    float sq = 0.f, sp = 0.f;
    for (int h = tid; h < Hh; h += 256) {
        float w = Wm[h];
        sq += qr[h]*w; sp += pr[h]*w;
    }
    for (int o = 16; o; o >>= 1) {
        sq += __shfl_down_sync(0xffffffffu, sq, o);
        sp += __shfl_down_sync(0xffffffffu, sp, o);
    }
    __shared__ float ssq[8], ssp[8];
    int w = tid >> 5, l = tid & 31;
    if (!l) { ssq[w] = sq; ssp[w] = sp; }
    __syncthreads();
    if (tid == 0) {
        float a = 0.f, c = 0.f;
        for (int i = 0; i < 8; i++) { a += ssq[i]; c += ssp[i]; }
        g_qWm[b*Tt + t] = a;
        g_pWm[b*Tt + t] = c;
    }
}

// ======== unified 128x128-tile batched GEMM: C[z] = A[z](MxK) @ W[z](KxN) ====
// A: row-major lda=K-pitch; W row-major pitch N. z batch: A += z*aStr,
// W += (z & wMask)*wStr, C += z*cStr. trans!=0 -> store C[n*ldcT + m] (ldcT=Tt).
__global__ void __launch_bounds__(256, 2) gemm128(
    const float* __restrict__ A, size_t aStr, int lda,
    const float* __restrict__ W, size_t wStr, int wMask, int N,
    float* __restrict__ C, size_t cStr, int K, int trans) {
    __shared__ float As[KB][132];
    __shared__ float Bs[KB][128];
    int z = blockIdx.z;
    int m0 = blockIdx.y * 128, n0 = blockIdx.x * 128;
    const float* Ab = A + (size_t)z * aStr;
    const float* Wb = W + (size_t)(z & wMask) * wStr;
    float* Cb = C + (size_t)z * cStr;

    int tid = threadIdx.x;
    int tx = tid & 15, ty = tid >> 4;
    uint64_t acc[8][4] = {};
    for (int k0 = 0; k0 < K; k0 += KB) {
        #pragma unroll
        for (int i = 0; i < 2; i++) {
            int idx = tid + i*256;            // 0..511
            int row = idx >> 2, c4 = (idx & 3) * 4;
            float4 a = *(const float4*)&Ab[(size_t)(m0 + row)*lda + k0 + c4];
            As[c4+0][row] = a.x; As[c4+1][row] = a.y;
            As[c4+2][row] = a.z; As[c4+3][row] = a.w;
        }
        #pragma unroll
        for (int i = 0; i < 2; i++) {
            int idx = tid + i*256;
            int krow = idx >> 5, col4 = (idx & 31) * 4;
            *(float4*)&Bs[krow][col4] =
                *(const float4*)&Wb[(size_t)(k0 + krow)*N + n0 + col4];
        }
        __syncthreads();
        #pragma unroll
        for (int k = 0; k < KB; k++) {
            float4 a0 = *(const float4*)&As[k][ty*4];
            float4 a1 = *(const float4*)&As[k][64 + ty*4];
            F4U2 b0; b0.f = *(const float4*)&Bs[k][tx*4];
            F4U2 b1; b1.f = *(const float4*)&Bs[k][64 + tx*4];
            float am[8] = {a0.x, a0.y, a0.z, a0.w, a1.x, a1.y, a1.z, a1.w};
            #pragma unroll
            for (int mi = 0; mi < 8; mi++) {
                uint64_t aa = bcast2(am[mi]);
                ffma2(acc[mi][0], aa, b0.u[0]);
                ffma2(acc[mi][1], aa, b0.u[1]);
                ffma2(acc[mi][2], aa, b1.u[0]);
                ffma2(acc[mi][3], aa, b1.u[1]);
            }
        }
        __syncthreads();
    }
    #pragma unroll
    for (int mi = 0; mi < 8; mi++) {
        int m = m0 + ((mi < 4) ? (ty*4 + mi) : (64 + ty*4 + mi - 4));
        #pragma unroll
        for (int np = 0; np < 4; np++) {
            int n = n0 + ((np < 2) ? (tx*4 + 2*np) : (64 + tx*4 + 2*(np - 2)));
            float c0, c1; unpack2(acc[mi][np], c0, c1);
            if (trans) {
                Cb[(size_t)(n + 0)*Tt + m] = c0;
                Cb[(size_t)(n + 1)*Tt + m] = c1;
            } else {
                float2 v = make_float2(c0, c1);
                *(float2*)&Cb[(size_t)m*N + n] = v;
            }
        }
    }
}

// ---- dual NT GEMM (128x64 tile, 8x4/thread): Sb = pb@q^T, Sd = tanh(..)*vd --
__global__ void __launch_bounds__(256, 2) gemm_bt2(
    const float* __restrict__ p, const float* __restrict__ q,
    const float* __restrict__ Wd, const float* __restrict__ vd) {
    __shared__ float As1[KB][132], As2[KB][132], Bs[KB][68];
    int b = blockIdx.z;
    int m0 = blockIdx.y * 128, n0 = blockIdx.x * 64;
    const float* pbb = g_pb + (size_t)b*Tt*Hh;
    const float* pr  = p   + (size_t)b*Tt*Hh;
    const float* qr  = q   + (size_t)b*Tt*Hh;
    int tid = threadIdx.x;
    int tx = tid & 15, ty = tid >> 4;
    uint64_t ab[8][2] = {}, ad[8][2] = {};
    for (int k0 = 0; k0 < Hh; k0 += KB) {
        #pragma unroll
        for (int i = 0; i < 2; i++) {
            int idx = tid + i*256;
            int row = idx >> 2, c4 = (idx & 3) * 4;
            float4 a1 = *(const float4*)&pbb[(size_t)(m0 + row)*Hh + k0 + c4];
            float4 a2 = *(const float4*)&pr [(size_t)(m0 + row)*Hh + k0 + c4];
            float4 wd = *(const float4*)&Wd[k0 + c4];
            As1[c4+0][row] = a1.x; As1[c4+1][row] = a1.y;
            As1[c4+2][row] = a1.z; As1[c4+3][row] = a1.w;
            As2[c4+0][row] = a2.x*wd.x; As2[c4+1][row] = a2.y*wd.y;
            As2[c4+2][row] = a2.z*wd.z; As2[c4+3][row] = a2.w*wd.w;
        }
        {
            int row = tid >> 2, c4 = (tid & 3) * 4;   // 64 rows x 16 k
            float4 bq = *(const float4*)&qr[(size_t)(n0 + row)*Hh + k0 + c4];
            Bs[c4+0][row] = bq.x; Bs[c4+1][row] = bq.y;
            Bs[c4+2][row] = bq.z; Bs[c4+3][row] = bq.w;
        }
        __syncthreads();
        #pragma unroll
        for (int k = 0; k < KB; k++) {
            float4 x0 = *(const float4*)&As1[k][ty*4];
            float4 x1 = *(const float4*)&As1[k][64 + ty*4];
            float4 y0 = *(const float4*)&As2[k][ty*4];
            float4 y1 = *(const float4*)&As2[k][64 + ty*4];
            F4U2 bb; bb.f = *(const float4*)&Bs[k][tx*4];
            float am1[8] = {x0.x, x0.y, x0.z, x0.w, x1.x, x1.y, x1.z, x1.w};
            float am2[8] = {y0.x, y0.y, y0.z, y0.w, y1.x, y1.y, y1.z, y1.w};
            #pragma unroll
            for (int mi = 0; mi < 8; mi++) {
                uint64_t aa1 = bcast2(am1[mi]);
                uint64_t aa2 = bcast2(am2[mi]);
                ffma2(ab[mi][0], aa1, bb.u[0]);
                ffma2(ab[mi][1], aa1, bb.u[1]);
                ffma2(ad[mi][0], aa2, bb.u[0]);
                ffma2(ad[mi][1], aa2, bb.u[1]);
            }
        }
        __syncthreads();
    }
    size_t base = (size_t)b*Tt*Tt;
    #pragma unroll
    for (int mi = 0; mi < 8; mi++) {
        int m = m0 + ((mi < 4) ? (ty*4 + mi) : (64 + ty*4 + mi - 4));
        #pragma unroll
        for (int np = 0; np < 2; np++) {
            int n = n0 + tx*4 + 2*np;
            float b0, b1; unpack2(ab[mi][np], b0, b1);
            float d0, d1; unpack2(ad[mi][np], d0, d1);
            *(float2*)&g_Sb[base + (size_t)m*Tt + n] = make_float2(b0, b1);
            g_Sd[base + (size_t)m*Tt + n + 0] = tanhf(d0) * vd[n + 0];
            g_Sd[base + (size_t)m*Tt + n + 1] = tanhf(d1) * vd[n + 1];
        }
    }
}

// ---------------- K3: finish scores + row softmax -> g_P ---------------------
__global__ void k_softmax(const float* __restrict__ vc, const float* __restrict__ vm) {
    int mode = blockIdx.z, b = blockIdx.y, i = blockIdx.x, j = threadIdx.x;
    size_t base = (size_t)b*Tt*Tt + (size_t)i*Tt;
    float s;
    if      (mode == 0) s = tanhf(g_whp[base + j] + g_whqT[base + j]) * vc[i];
    else if (mode == 1) s = g_Sb[base + j];
    else if (mode == 2) s = g_Sd[base + j];
    else                s = tanhf(g_qWm[b*Tt + j] - g_pWm[b*Tt + i]) * vm[j];

    float m = s;
    for (int o = 16; o; o >>= 1) m = fmaxf(m, __shfl_xor_sync(0xffffffffu, m, o));
    __shared__ float rm[8], rs[8];
    int w = j >> 5, l = j & 31;
    if (!l) rm[w] = m;
    __syncthreads();
    float mm = rm[0];
    #pragma unroll
    for (int k = 1; k < 8; k++) mm = fmaxf(mm, rm[k]);

    float e = __expf(s - mm);
    float sum = e;
    for (int o = 16; o; o >>= 1) sum += __shfl_xor_sync(0xffffffffu, sum, o);
    if (!l) rs[w] = sum;
    __syncthreads();
    float tot = 0.f;
    #pragma unroll
    for (int k = 0; k < 8; k++) tot += rs[k];

    g_P[(size_t)mode*Bb*Tt*Tt + base + j] = e / tot;
}

// ---------------- launch -----------------------------------------------------
extern "C" void kernel_launch(void* const* d_in, const int* in_sizes, int n_in,
                              void* d_out, int out_size) {
    const float* q   = (const float*)d_in[0];
    const float* p   = (const float*)d_in[1];
    const float* Wc1 = (const float*)d_in[2];
    const float* Wc2 = (const float*)d_in[3];
    const float* vc  = (const float*)d_in[4];
    const float* Wb  = (const float*)d_in[5];
    const float* Wd  = (const float*)d_in[6];
    const float* vd  = (const float*)d_in[7];
    const float* Wm  = (const float*)d_in[8];
    const float* vm  = (const float*)d_in[9];
    float* out = (float*)d_out;

    float* d_whqT; cudaGetSymbolAddress((void**)&d_whqT, g_whqT);
    float* d_whp;  cudaGetSymbolAddress((void**)&d_whp,  g_whp);
    float* d_pb;   cudaGetSymbolAddress((void**)&d_pb,   g_pb);
    float* d_P;    cudaGetSymbolAddress((void**)&d_P,    g_P);

    k_vec<<<dim3(Tt, Bb), 256>>>(q, p, Wm);
    // whqT[b] = (q[b] @ Wc1) stored transposed
    gemm128<<<dim3(2, 2, Bb), 256>>>(q, (size_t)Tt*Hh, Hh,
                                     Wc1, 0, 0, Tt,
                                     d_whqT, (size_t)Tt*Tt, Hh, 1);
    // whp[b] = p[b] @ Wc2
    gemm128<<<dim3(2, 2, Bb), 256>>>(p, (size_t)Tt*Hh, Hh,
                                     Wc2, 0, 0, Tt,
                                     d_whp, (size_t)Tt*Tt, Hh, 0);
    // pb[b] = p[b] @ Wb
    gemm128<<<dim3(6, 2, Bb), 256>>>(p, (size_t)Tt*Hh, Hh,
                                     Wb, 0, 0, Hh,
                                     d_pb, (size_t)Tt*Hh, Hh, 0);
    // Sb, Sd
    gemm_bt2<<<dim3(4, 2, Bb), 256>>>(p, q, Wd, vd);
    // 4x softmax
    k_softmax<<<dim3(Tt, Bb, 4), 256>>>(vc, vm);
    // out[z] = P[z] @ q[z&63], z = type*64 + b
    gemm128<<<dim3(6, 2, 4*Bb), 256>>>(d_P, (size_t)Tt*Tt, Tt,
                                       q, (size_t)Tt*Hh, 63, Hh,
                                       out, (size_t)Tt*Hh, Tt, 0);
}